// round 14
// baseline (speedup 1.0000x reference)
#include <cuda_runtime.h>

#define N_PTS   4096
#define PAIRS   8
#define TPB     256
#define T_DIM   4
#define INV_SCALE (1.0f / (T_DIM * N_PTS))
#define FINF    3.0e38f

#define NB      128                       // z-buckets
#define ZR      4.25f
#define BW      (2.0f * ZR / NB)
#define INV_BW  (NB / (2.0f * ZR))

// Sorted-by-z copies: (x, y, z, |p|^2). 1 MB total.
__device__ float4 g_sA[PAIRS * N_PTS];
__device__ float4 g_sB[PAIRS * N_PTS];
__device__ int    g_bstart[PAIRS][NB + 1];

__device__ __forceinline__ int zbucket(float z) {
    int b = (int)floorf((z + ZR) * INV_BW);
    return min(max(b, 0), NB - 1);
}

// ---------------------------------------------------------------------------
// Counting sort by z. One block per (set, pair); 16 blocks total.
// ---------------------------------------------------------------------------
__global__ __launch_bounds__(TPB)
void hd_sort(const float* __restrict__ d1,
             const float* __restrict__ d2,
             float* __restrict__ out) {
    __shared__ int hist[NB];
    __shared__ int start[NB + 1];
    __shared__ int ofs[NB];

    const int set  = blockIdx.x & 1;       // 0 = data1 (queries), 1 = data2 (targets)
    const int pair = blockIdx.x >> 1;
    const float* src = (set ? d2 : d1) + (size_t)pair * N_PTS * 3;
    float4* dst = (set ? g_sB : g_sA) + (size_t)pair * N_PTS;

    if (blockIdx.x == 0 && threadIdx.x < 2) out[threadIdx.x] = 0.0f;

    for (int b = threadIdx.x; b < NB; b += TPB) hist[b] = 0;
    __syncthreads();

    float px[16], py[16], pz[16];
    int   pb[16];
    #pragma unroll
    for (int k = 0; k < 16; ++k) {
        const int p = threadIdx.x + k * TPB;
        px[k] = src[3 * p + 0];
        py[k] = src[3 * p + 1];
        pz[k] = src[3 * p + 2];
        pb[k] = zbucket(pz[k]);
        atomicAdd(&hist[pb[k]], 1);
    }
    __syncthreads();

    if (threadIdx.x == 0) {
        int s = 0;
        for (int b = 0; b < NB; ++b) { start[b] = s; s += hist[b]; }
        start[NB] = s;                    // == N_PTS
    }
    __syncthreads();
    for (int b = threadIdx.x; b < NB; b += TPB) ofs[b] = start[b];
    __syncthreads();

    #pragma unroll
    for (int k = 0; k < 16; ++k) {
        const int pos = atomicAdd(&ofs[pb[k]], 1);
        const float w = fmaf(px[k], px[k], fmaf(py[k], py[k], pz[k] * pz[k]));
        dst[pos] = make_float4(px[k], py[k], pz[k], w);
    }

    if (set == 1 && threadIdx.x <= NB)
        g_bstart[pair][threadIdx.x] = start[threadIdx.x];
}

// ---------------------------------------------------------------------------
// Pruned NN search. Grid (16, PAIRS): 16 blocks x 256 threads = 4096 queries
// per pair; set-2 (sorted, with bucket index) staged in 64 KB dynamic smem.
// ---------------------------------------------------------------------------
__global__ __launch_bounds__(TPB)
void hd_search(float* __restrict__ out) {
    extern __shared__ float4 sb[];        // N_PTS sorted targets
    __shared__ int   sstart[NB + 1];
    __shared__ float red[TPB / 32];

    cudaGridDependencySynchronize();      // wait for hd_sort (PDL)

    const int pair = blockIdx.y;

    for (int idx = threadIdx.x; idx < N_PTS; idx += TPB)
        sb[idx] = g_sB[(size_t)pair * N_PTS + idx];
    if (threadIdx.x <= NB)
        sstart[threadIdx.x] = g_bstart[pair][threadIdx.x];
    __syncthreads();

    const int i = blockIdx.x * TPB + threadIdx.x;
    const float4 a = g_sA[(size_t)pair * N_PTS + i];
    const float na2 = a.w;
    const float axn = -2.0f * a.x;
    const float ayn = -2.0f * a.y;
    const float azn = -2.0f * a.z;
    const int   zb  = zbucket(a.z);

    // mt = min over candidates of (|b|^2 - 2 a.b);  d^2 = na2 + mt
    float mt = FINF;

    // own bucket
    {
        const int e = sstart[zb + 1];
        for (int idx = sstart[zb]; idx < e; ++idx) {
            float4 q = sb[idx];
            float t = fmaf(axn, q.x, q.w);
            t = fmaf(ayn, q.y, t);
            t = fmaf(azn, q.z, t);
            mt = fminf(mt, t);
        }
    }

    // expand rings; per-side sticky termination on provable z-gap bound
    bool doneR = false, doneL = false;
    for (int k = 1; k < NB && !(doneR && doneL); ++k) {
        const int r = zb + k;
        if (!doneR) {
            if (r >= NB) doneR = true;
            else {
                const float lb = fmaxf(0.0f, (-ZR + r * BW) - a.z);
                if (fmaf(lb, lb, -na2) > mt) doneR = true;
                else {
                    const int e = sstart[r + 1];
                    for (int idx = sstart[r]; idx < e; ++idx) {
                        float4 q = sb[idx];
                        float t = fmaf(axn, q.x, q.w);
                        t = fmaf(ayn, q.y, t);
                        t = fmaf(azn, q.z, t);
                        mt = fminf(mt, t);
                    }
                }
            }
        }
        const int l = zb - k;
        if (!doneL) {
            if (l < 0) doneL = true;
            else {
                const float lb = fmaxf(0.0f, a.z - (-ZR + (l + 1) * BW));
                if (fmaf(lb, lb, -na2) > mt) doneL = true;
                else {
                    const int e = sstart[l + 1];
                    for (int idx = sstart[l]; idx < e; ++idx) {
                        float4 q = sb[idx];
                        float t = fmaf(axn, q.x, q.w);
                        t = fmaf(ayn, q.y, t);
                        t = fmaf(azn, q.z, t);
                        mt = fminf(mt, t);
                    }
                }
            }
        }
    }

    float acc = sqrtf(fmaxf(na2 + mt, 0.0f));

    #pragma unroll
    for (int off = 16; off > 0; off >>= 1)
        acc += __shfl_xor_sync(0xFFFFFFFFu, acc, off);

    const int lane = threadIdx.x & 31;
    const int wid  = threadIdx.x >> 5;
    if (lane == 0) red[wid] = acc;
    __syncthreads();

    if (wid == 0) {
        float v = (lane < TPB / 32) ? red[lane] : 0.0f;
        #pragma unroll
        for (int off = 4; off > 0; off >>= 1)
            v += __shfl_xor_sync(0xFFFFFFFFu, v, off);
        if (lane == 0)
            atomicAdd(&out[pair >> 2], v * INV_SCALE);
    }
}

extern "C" void kernel_launch(void* const* d_in, const int* in_sizes, int n_in,
                              void* d_out, int out_size) {
    const float* d1 = (const float*)d_in[0];
    const float* d2 = (const float*)d_in[1];
    float* out = (float*)d_out;

    static const size_t kSmem = (size_t)N_PTS * sizeof(float4);   // 64 KB
    cudaFuncSetAttribute(hd_search, cudaFuncAttributeMaxDynamicSharedMemorySize,
                         (int)kSmem);

    hd_sort<<<2 * PAIRS, TPB>>>(d1, d2, out);

    cudaLaunchConfig_t cfg = {};
    cfg.gridDim  = dim3(N_PTS / TPB, PAIRS);   // (16, 8)
    cfg.blockDim = dim3(TPB);
    cfg.dynamicSmemBytes = kSmem;
    cudaLaunchAttribute attr[1];
    attr[0].id = cudaLaunchAttributeProgrammaticStreamSerialization;
    attr[0].val.programmaticStreamSerializationAllowed = 1;
    cfg.attrs = attr;
    cfg.numAttrs = 1;
    cudaLaunchKernelEx(&cfg, hd_search, out);
}

// round 16
// speedup vs baseline: 1.2159x; 1.2159x over previous
#include <cuda_runtime.h>

#define N_PTS   4096
#define PAIRS   8
#define TPB     256
#define T_DIM   4
#define INV_SCALE (1.0f / (T_DIM * N_PTS))
#define FINF    3.0e38f

#define NC      32                        // cells per axis (y, z)
#define NC2     (NC * NC)                 // 1024 cells
#define ZR      4.25f
#define CW      (2.0f * ZR / NC)          // 0.265625
#define INV_CW  (NC / (2.0f * ZR))

// Sorted-by-cell copies: (x, y, z, |p|^2). 1 MB total.
__device__ float4 g_sA[PAIRS * N_PTS];
__device__ float4 g_sB[PAIRS * N_PTS];
__device__ int    g_cellstart[PAIRS][NC2 + 1];

__device__ __forceinline__ int caxis(float v) {
    int c = (int)floorf((v + ZR) * INV_CW);
    return min(max(c, 0), NC - 1);
}

// ---------------------------------------------------------------------------
// Counting sort by (y,z) cell id. One block per (set, pair); 16 blocks.
// ---------------------------------------------------------------------------
__global__ __launch_bounds__(TPB)
void hd_sort(const float* __restrict__ d1,
             const float* __restrict__ d2,
             float* __restrict__ out) {
    __shared__ int hist[NC2];
    __shared__ int start[NC2 + 1];
    __shared__ int ofs[NC2];
    __shared__ int warpsums[TPB / 32];

    const int set  = blockIdx.x & 1;       // 0 = data1 (queries), 1 = data2 (targets)
    const int pair = blockIdx.x >> 1;
    const float* src = (set ? d2 : d1) + (size_t)pair * N_PTS * 3;
    float4* dst = (set ? g_sB : g_sA) + (size_t)pair * N_PTS;

    if (blockIdx.x == 0 && threadIdx.x < 2) out[threadIdx.x] = 0.0f;

    for (int c = threadIdx.x; c < NC2; c += TPB) hist[c] = 0;
    __syncthreads();

    float px[16], py[16], pz[16];
    int   pc[16];
    #pragma unroll
    for (int k = 0; k < 16; ++k) {
        const int p = threadIdx.x + k * TPB;
        px[k] = src[3 * p + 0];
        py[k] = src[3 * p + 1];
        pz[k] = src[3 * p + 2];
        pc[k] = caxis(py[k]) * NC + caxis(pz[k]);
        atomicAdd(&hist[pc[k]], 1);
    }
    __syncthreads();

    // Exclusive prefix scan of hist[1024]: 4 cells per thread + block scan.
    {
        const int c0 = 4 * threadIdx.x;
        const int s0 = hist[c0], s1 = hist[c0 + 1], s2 = hist[c0 + 2], s3 = hist[c0 + 3];
        const int csum = s0 + s1 + s2 + s3;
        const int lane = threadIdx.x & 31;
        const int wid  = threadIdx.x >> 5;

        int incl = csum;
        #pragma unroll
        for (int off = 1; off < 32; off <<= 1) {
            int n = __shfl_up_sync(0xFFFFFFFFu, incl, off);
            if (lane >= off) incl += n;
        }
        if (lane == 31) warpsums[wid] = incl;
        __syncthreads();
        if (threadIdx.x == 0) {
            int acc = 0;
            #pragma unroll
            for (int w = 0; w < TPB / 32; ++w) {
                int t = warpsums[w]; warpsums[w] = acc; acc += t;
            }
        }
        __syncthreads();
        int excl = incl - csum + warpsums[wid];
        start[c0]     = excl;
        start[c0 + 1] = excl + s0;
        start[c0 + 2] = excl + s0 + s1;
        start[c0 + 3] = excl + s0 + s1 + s2;
        if (threadIdx.x == 0) start[NC2] = N_PTS;
    }
    __syncthreads();
    for (int c = threadIdx.x; c < NC2; c += TPB) ofs[c] = start[c];
    __syncthreads();

    #pragma unroll
    for (int k = 0; k < 16; ++k) {
        const int pos = atomicAdd(&ofs[pc[k]], 1);
        const float w = fmaf(px[k], px[k], fmaf(py[k], py[k], pz[k] * pz[k]));
        dst[pos] = make_float4(px[k], py[k], pz[k], w);
    }

    if (set == 1)
        for (int c = threadIdx.x; c <= NC2; c += TPB)
            g_cellstart[pair][c] = start[c];
}

// ---------------------------------------------------------------------------
// Exact pruned NN search via expanding cell rings in (y,z).
// Grid (16, PAIRS), 256 thr, 1 query/thread; targets staged in 64 KB smem.
// ---------------------------------------------------------------------------
__global__ __launch_bounds__(TPB)
void hd_search(float* __restrict__ out) {
    extern __shared__ float4 sb[];        // N_PTS sorted targets (64 KB)
    __shared__ int   scs[NC2 + 1];
    __shared__ float red[TPB / 32];

    const int pair = blockIdx.y;

    {
        const float4* src = g_sB + (size_t)pair * N_PTS;
        #pragma unroll
        for (int k = 0; k < N_PTS / TPB; ++k)
            sb[threadIdx.x + k * TPB] = src[threadIdx.x + k * TPB];
    }
    for (int c = threadIdx.x; c <= NC2; c += TPB)
        scs[c] = g_cellstart[pair][c];
    __syncthreads();

    const int i = blockIdx.x * TPB + threadIdx.x;
    const float4 a = g_sA[(size_t)pair * N_PTS + i];
    const float na2 = a.w;
    const float axn = -2.0f * a.x;
    const float ayn = -2.0f * a.y;
    const float azn = -2.0f * a.z;
    const int cy = caxis(a.y);
    const int cz = caxis(a.z);

    // mt = min over candidates of (|b|^2 - 2 a.b);  d^2 = na2 + mt
    float mt = FINF;

    #define SCAN_CELL(YY, ZZ) do {                                   \
        const int cid = (YY) * NC + (ZZ);                             \
        const int e_ = scs[cid + 1];                                  \
        for (int idx = scs[cid]; idx < e_; ++idx) {                   \
            float4 q = sb[idx];                                       \
            float t = fmaf(axn, q.x, q.w);                            \
            t = fmaf(ayn, q.y, t);                                    \
            t = fmaf(azn, q.z, t);                                    \
            mt = fminf(mt, t);                                        \
        }                                                             \
    } while (0)

    SCAN_CELL(cy, cz);                     // ring 0

    for (int R = 1; R <= NC; ++R) {
        const float gap = (R - 1) * CW;    // lower bound on dist to ring-R cells
        if (fmaf(gap, gap, -na2) > mt) break;

        const int zlo = cz - R, zhi = cz + R;
        const int ylo = cy - R, yhi = cy + R;
        for (int yy = max(ylo, 0); yy <= min(yhi, NC - 1); ++yy) {
            if (zhi < NC) SCAN_CELL(yy, zhi);
            if (zlo >= 0) SCAN_CELL(yy, zlo);
        }
        for (int zz = max(zlo + 1, 0); zz <= min(zhi - 1, NC - 1); ++zz) {
            if (yhi < NC) SCAN_CELL(yhi, zz);
            if (ylo >= 0) SCAN_CELL(ylo, zz);
        }
    }
    #undef SCAN_CELL

    float acc = sqrtf(fmaxf(na2 + mt, 0.0f));

    #pragma unroll
    for (int off = 16; off > 0; off >>= 1)
        acc += __shfl_xor_sync(0xFFFFFFFFu, acc, off);

    const int lane = threadIdx.x & 31;
    const int wid  = threadIdx.x >> 5;
    if (lane == 0) red[wid] = acc;
    __syncthreads();

    if (wid == 0) {
        float v = (lane < TPB / 32) ? red[lane] : 0.0f;
        #pragma unroll
        for (int off = 4; off > 0; off >>= 1)
            v += __shfl_xor_sync(0xFFFFFFFFu, v, off);
        if (lane == 0)
            atomicAdd(&out[pair >> 2], v * INV_SCALE);
    }
}

extern "C" void kernel_launch(void* const* d_in, const int* in_sizes, int n_in,
                              void* d_out, int out_size) {
    const float* d1 = (const float*)d_in[0];
    const float* d2 = (const float*)d_in[1];
    float* out = (float*)d_out;

    static const size_t kSmem = (size_t)N_PTS * sizeof(float4);   // 64 KB
    cudaFuncSetAttribute(hd_search, cudaFuncAttributeMaxDynamicSharedMemorySize,
                         (int)kSmem);

    hd_sort<<<2 * PAIRS, TPB>>>(d1, d2, out);
    hd_search<<<dim3(N_PTS / TPB, PAIRS), TPB, kSmem>>>(out);
}